// round 16
// baseline (speedup 1.0000x reference)
#include <cuda_runtime.h>
#include <cuda_bf16.h>

#define MAX_LEN_SEQ 2048
#define T_PAD       2176
#define MIN_SEG     32
#define S_          65
#define B_          16
#define D_          128
#define R_          1040
#define W_          256

__device__ int g_offset[R_];
__device__ int g_rowstart[R_ + 1];
__device__ int g_L;

// ---------------------------------------------------------------------------
// Kernel A: single block. Per-row masked-prefix counts (candidate + exact
// fp32 predicate fix-up, bit-identical to the reference mask), per-batch
// segment offsets, global exclusive scan -> g_rowstart / g_L.
// ---------------------------------------------------------------------------
__global__ __launch_bounds__(1024) void k_meta(const float* __restrict__ scales,
                                               const int*   __restrict__ len_seq,
                                               const int*   __restrict__ len_seg_raw) {
    __shared__ int sh_len[R_];
    __shared__ int sh_off[R_];
    __shared__ int sh_cnt[R_];
    __shared__ int sh_lseq[B_];
    int tid  = threadIdx.x;
    int wid  = tid >> 5;
    int lane = tid & 31;

    if (tid < R_) sh_len[tid] = len_seg_raw[tid] + MIN_SEG;
    if (tid < 16) sh_len[1024 + tid] = len_seg_raw[1024 + tid] + MIN_SEG;
    if (tid < B_) sh_lseq[tid] = len_seq[tid];
    __syncthreads();

    // per-batch exclusive offsets via warp shuffle scans (warp b = batch b)
    if (wid < B_) {
        int base = wid * S_;
        int v0 = sh_len[base + lane];
        int v1 = sh_len[base + 32 + lane];
        int s0 = v0, s1 = v1;
        #pragma unroll
        for (int d = 1; d < 32; d <<= 1) {
            int u0 = __shfl_up_sync(0xffffffffu, s0, d);
            int u1 = __shfl_up_sync(0xffffffffu, s1, d);
            if (lane >= d) { s0 += u0; s1 += u1; }
        }
        int tot0 = __shfl_sync(0xffffffffu, s0, 31);
        int tot1 = __shfl_sync(0xffffffffu, s1, 31);
        int e0 = s0 - v0;
        int e1 = tot0 + (s1 - v1);
        sh_off[base + lane]      = e0;
        sh_off[base + 32 + lane] = e1;
        g_offset[base + lane]      = e0;
        g_offset[base + 32 + lane] = e1;
        if (lane == 0) {
            sh_off[base + 64]   = tot0 + tot1;
            g_offset[base + 64] = tot0 + tot1;
        }
    }
    __syncthreads();

    // per-row counts (candidate + exact-predicate fix-up)
    for (int r = tid; r < R_; r += 1024) {
        int b   = r / S_;
        int lim = min(sh_len[r] - 1, sh_lseq[b] - 1 - sh_off[r]);
        int cnt = 0;
        if (lim > 0) {
            float sc   = __ldg(&scales[r]) + 0.5f;
            float limf = (float)lim;
            int cand = (int)ceilf(sc * limf);
            cand = max(0, min(cand, W_));
            while (cand < W_ && ((float)cand / sc) < limf) cand++;
            while (cand > 0 && ((float)(cand - 1) / sc) >= limf) cand--;
            cnt = cand;
        }
        sh_cnt[r] = cnt;
    }
    __syncthreads();

    // exclusive scan of 1040 counts
    if (tid < 32) {
        const int CH = 33;
        int base = tid * CH;
        int s = 0;
        #pragma unroll
        for (int j = 0; j < CH; j++) {
            int i = base + j;
            if (i < R_) s += sh_cnt[i];
        }
        int incl = s;
        #pragma unroll
        for (int d = 1; d < 32; d <<= 1) {
            int v = __shfl_up_sync(0xffffffffu, incl, d);
            if (tid >= d) incl += v;
        }
        int run = incl - s;
        #pragma unroll
        for (int j = 0; j < CH; j++) {
            int i = base + j;
            if (i < R_) { g_rowstart[i] = run; run += sh_cnt[i]; }
        }
        if (tid == 31) {
            g_rowstart[R_] = run;
            g_L = run / B_;
        }
    }
}

// ---------------------------------------------------------------------------
// Kernel B (forward scatter): block r < R_ owns segment row r and its
// CONTIGUOUS output-slot range [rowstart[r], rowstart[r]+count). Warp wid
// sweeps w = wid, wid+8, ... (independent iterations -> pipelined loads).
// Blocks r >= R_ zero-fill the t >= L tail (disjoint rows, no hazard).
// ---------------------------------------------------------------------------
#define ZBLOCKS 1024
__global__ __launch_bounds__(256) void k_scatter(const float* __restrict__ x,
                                                 const float* __restrict__ scales,
                                                 float* __restrict__ out) {
    int lane = threadIdx.x & 31;
    int wid  = threadIdx.x >> 5;
    int L = g_L;

    if (blockIdx.x >= R_) {
        // ---- zero-fill: 32 output rows per block, 4 per warp ----
        int zbase = (blockIdx.x - R_) * 32 + wid * 4;
        float4 z = make_float4(0.f, 0.f, 0.f, 0.f);
        #pragma unroll
        for (int j = 0; j < 4; j++) {
            int row = zbase + j;                 // 0..32767
            int t = row & (MAX_LEN_SEQ - 1);
            if (t >= L) {
                float4* orow = reinterpret_cast<float4*>(out + (size_t)row * D_);
                orow[lane] = z;
            }
        }
        return;
    }

    int r   = blockIdx.x;
    int rs  = __ldg(&g_rowstart[r]);
    int cnt = __ldg(&g_rowstart[r + 1]) - rs;
    if (cnt <= 0) return;

    float sc = __ldg(&scales[r]) + 0.5f;
    int  off = __ldg(&g_offset[r]);
    int bsrc = r / S_;
    const float* xb = x + (size_t)bsrc * T_PAD * D_;

    #pragma unroll 2
    for (int w = wid; w < cnt; w += 8) {
        int g = rs + w;
        int b_out = g / L;                       // slot -> (b_out, t)
        int t = g - b_out * L;
        if (b_out >= B_ || t >= MAX_LEN_SEQ) continue;

        float idx_scaled = (float)w / sc;        // exact reference fp32 ops
        float idx_fl = floorf(idx_scaled);
        float lam = idx_scaled - idx_fl;
        int i_fl = (int)idx_fl + off;
        if (i_fl > T_PAD - 1) i_fl = T_PAD - 1;
        int i_cl = min(i_fl + 1, T_PAD - 1);

        const float4* pa = reinterpret_cast<const float4*>(xb + (size_t)i_fl * D_) + lane;
        const float4* pc = reinterpret_cast<const float4*>(xb + (size_t)i_cl * D_) + lane;
        float4 va = __ldg(pa);
        float4 vc = __ldg(pc);
        float om = 1.0f - lam;
        float4 vy;
        vy.x = om * va.x + lam * vc.x;
        vy.y = om * va.y + lam * vc.y;
        vy.z = om * va.z + lam * vc.z;
        vy.w = om * va.w + lam * vc.w;
        float4* orow = reinterpret_cast<float4*>(out + ((size_t)b_out * MAX_LEN_SEQ + t) * D_);
        orow[lane] = vy;
    }
}

extern "C" void kernel_launch(void* const* d_in, const int* in_sizes, int n_in,
                              void* d_out, int out_size) {
    const float* x           = (const float*)d_in[0];
    const float* scales      = (const float*)d_in[1];
    const int*   len_seq     = (const int*)d_in[2];
    const int*   len_seg_raw = (const int*)d_in[3];
    float* out = (float*)d_out;

    k_meta<<<1, 1024>>>(scales, len_seq, len_seg_raw);
    k_scatter<<<R_ + ZBLOCKS, 256>>>(x, scales, out);
}